// round 15
// baseline (speedup 1.0000x reference)
#include <cuda_runtime.h>
#include <cuda_fp16.h>
#include <cstdint>

// NeuralSpectralBlock1d: fp16 mma.sync GEMM with A-operand streamed DIRECTLY from
// global in register-fragment order (no cp.async, no A-ldmatrix, no ring, no
// barriers in chunk loop) + packed f32x2 Chebyshev epilogue. 2 CTAs/SM.
// CTA = 64 columns (16 patches) of one batch. Grid 2048, 256 threads.

#define THREADS 256

// SMEM layout (total 114176 B -> 2 CTAs/SM)
#define XTHI 0u          // x^T fp16 [64 j][256 k], 16B-swizzled       (32768)
#define AST  32768u      // epilogue stg_t [64 pos][528B]               (33792)
#define LTT  66560u      // lt_t fp16 [64 tok][528B]                    (33792)
#define WS   100352u     // spectral weights half2-pairs [128 pid][24]  (12288)
#define EB   112640u     // enc bias fp16 [512]                         (1024)
#define DB   113664u     // dec bias fp16 [256]                         (512)
#define SMEM_REQ 114176u

#define TSB 528u         // transposed row stride in bytes (264 halves)

typedef unsigned long long ull;

// Pre-fragmented fp16 weights in m16n8k16 A-fragment lane order.
// slice s (0..23) = rows s*32..s*32+31 (rows 0-511 enc, 512-767 dec).
// g_wfrag[s][chunk][hf*32 + lane]: hf=0 -> rows base..base+15 (mt0), hf=1 -> mt1.
// uint4 = {a0,a1,a2,a3}: a0=(row l/4, k k0,k0+1), a1=(row+8, same k),
//                        a2=(row l/4, k0+8,k0+9), a3=(row+8, k0+8,k0+9), k0=(l%4)*2.
__device__ uint4 g_wfrag[24][16][64];

__global__ void prep_kernel(const float* __restrict__ enc_w, const float* __restrict__ dec_w) {
    int idx = blockIdx.x * blockDim.x + threadIdx.x;
    if (idx >= 24 * 16 * 64) return;
    int slice = idx >> 10;
    int rem = idx & 1023;
    int c = rem >> 6;
    int hf = (rem >> 5) & 1;
    int l = rem & 31;
    int g = slice * 32 + hf * 16 + (l >> 2);
    int k0 = c * 16 + (l & 3) * 2;
    const float* r0 = (g < 512) ? (enc_w + g * 256) : (dec_w + (g - 512) * 256);
    const float* r8 = r0 + 8 * 256;   // g and g+8 always in same matrix (slice-aligned)
    uint4 u;
    __half2 h;
    h = __floats2half2_rn(r0[k0],     r0[k0 + 1]); u.x = *(uint32_t*)&h;
    h = __floats2half2_rn(r8[k0],     r8[k0 + 1]); u.y = *(uint32_t*)&h;
    h = __floats2half2_rn(r0[k0 + 8], r0[k0 + 9]); u.z = *(uint32_t*)&h;
    h = __floats2half2_rn(r8[k0 + 8], r8[k0 + 9]); u.w = *(uint32_t*)&h;
    g_wfrag[slice][c][hf * 32 + l] = u;
}

static __device__ __forceinline__ uint32_t smem_u32(const void* p) {
    uint32_t a;
    asm("{ .reg .u64 t; cvta.to.shared.u64 t, %1; cvt.u32.u64 %0, t; }" : "=r"(a) : "l"(p));
    return a;
}
static __device__ __forceinline__ void ldm4(uint32_t* d, uint32_t a) {
    asm volatile("ldmatrix.sync.aligned.m8n8.x4.shared.b16 {%0,%1,%2,%3}, [%4];"
                 : "=r"(d[0]), "=r"(d[1]), "=r"(d[2]), "=r"(d[3]) : "r"(a));
}
static __device__ __forceinline__ void mma16816(float* c, const uint32_t* a, const uint32_t* b) {
    asm volatile("mma.sync.aligned.m16n8k16.row.col.f32.f16.f16.f32 "
                 "{%0,%1,%2,%3}, {%4,%5,%6,%7}, {%8,%9}, {%0,%1,%2,%3};"
                 : "+f"(c[0]), "+f"(c[1]), "+f"(c[2]), "+f"(c[3])
                 : "r"(a[0]), "r"(a[1]), "r"(a[2]), "r"(a[3]), "r"(b[0]), "r"(b[1]));
}

// ---- packed f32x2 helpers ----
static __device__ __forceinline__ ull pk2(float lo, float hi) {
    ull r; asm("mov.b64 %0, {%1, %2};" : "=l"(r) : "f"(lo), "f"(hi)); return r;
}
static __device__ __forceinline__ ull pk2h(__half2 h) {
    float2 f = __half22float2(h); return pk2(f.x, f.y);
}
static __device__ __forceinline__ void upk2(float& lo, float& hi, ull v) {
    asm("mov.b64 {%0, %1}, %2;" : "=f"(lo), "=f"(hi) : "l"(v));
}
static __device__ __forceinline__ ull f2fma(ull a, ull b, ull c) {
    ull d; asm("fma.rn.f32x2 %0, %1, %2, %3;" : "=l"(d) : "l"(a), "l"(b), "l"(c)); return d;
}
static __device__ __forceinline__ ull f2add(ull a, ull b) {
    ull d; asm("add.rn.f32x2 %0, %1, %2;" : "=l"(d) : "l"(a), "l"(b)); return d;
}

__global__ __launch_bounds__(THREADS, 2)
void NeuralSpectralBlock1d_4509715661385_kernel(
    const float* __restrict__ x, const float* __restrict__ weights,
    const float* __restrict__ latent, const float* __restrict__ enc_b,
    const float* __restrict__ dec_b, float* __restrict__ out)
{
    extern __shared__ char smem[];
    const uint32_t sb = smem_u32(smem);

    __half2* wsp2 = (__half2*)(smem + WS);   // [128 pid][24] pairs {w[ch0][m], w[ch0+4][m]}
    __half*  eb_h = (__half*)(smem + EB);
    __half*  db_h = (__half*)(smem + DB);

    const int tid = threadIdx.x;
    const int wid = tid >> 5, lid = tid & 31;
    const int bx = blockIdx.x;
    const int batch = bx >> 6;
    const int hp0 = (bx & 63) * 16;
    const int h0 = hp0 * 4;
    const float* xg = x + (size_t)batch * 256 * 4096 + h0;
    float* og = out + (size_t)batch * 256 * 4096;

    // ---- loads: x tile fp16 swizzled, spectral weight pairs, biases ----
    for (int idx = tid; idx < 64 * 256; idx += THREADS) {
        int j = idx & 63, c = idx >> 6;
        float v = xg[(size_t)c * 4096 + j];
        uint32_t off = (uint32_t)j * 512u + ((uint32_t)((c >> 3) ^ (j & 7)) << 4) + (uint32_t)(c & 7) * 2u;
        *(__half*)(smem + XTHI + off) = __float2half(v);
    }
    // spectral weights, pair layout: pid = h*16 + p*4 + lb -> channels (ch0, ch0+4),
    // ch0 = h*32 + lb + 8p. wsp2[pid*24 + m] = {w[ch0][m], w[ch0+4][m]}
    for (int idx = tid; idx < 128 * 24; idx += THREADS) {
        int pid = idx / 24, m = idx - pid * 24;
        int lb_ = pid & 3, p_ = (pid >> 2) & 3, h_ = pid >> 4;
        int ch0 = h_ * 32 + lb_ + 8 * p_;
        wsp2[idx] = __floats2half2_rn(weights[ch0 * 24 + m], weights[(ch0 + 4) * 24 + m]);
    }
    for (int idx = tid; idx < 512; idx += THREADS) eb_h[idx] = __float2half(enc_b[idx]);
    for (int idx = tid; idx < 256; idx += THREADS) db_h[idx] = __float2half(dec_b[idx]);
    __syncthreads();

    const unsigned FULL = 0xFFFFFFFFu;
    const float PI_OVER_NB = 0.26179938779914943653855361527329f;  // pi/12
    const ull SGN2 = 0x8000000080000000ULL;

    // epilogue lane roles
    const int ip = tid >> 4;
    const int lane4 = tid & 15;
    const int la = lane4 >> 2, lb = lane4 & 3;

    // GEMM roles: warp wid owns rows wid*32..+31 (slice r*8+wid), all 64 cols
    const int b_n8 = (lid & 7) + ((lid >> 4) & 1) * 8;
    const int b_k8 = (lid >> 3) & 1;

    // ================= 3 GEMM rounds: r=0,1 enc; r=2 dec =================
#pragma unroll 1
    for (int r = 0; r < 3; r++) {
        float acc[2][8][4];
#pragma unroll
        for (int mt = 0; mt < 2; mt++)
#pragma unroll
            for (int nt = 0; nt < 8; nt++)
#pragma unroll
                for (int q = 0; q < 4; q++) acc[mt][nt][q] = 0.f;

        // ---- barrier-free chunk loop: A direct from global (fragment order) ----
        const uint4* __restrict__ wptr = &g_wfrag[r * 8 + wid][0][lid];
        uint4 pa0 = wptr[0],  pb0 = wptr[32];
        uint4 pa1 = wptr[64], pb1 = wptr[96];
#pragma unroll 2
        for (int c = 0; c < 16; c++) {
            uint4 ca = pa0, cb = pb0;
            pa0 = pa1; pb0 = pb1;
            if (c < 14) {
                const uint4* np = wptr + (c + 2) * 64;
                pa1 = np[0]; pb1 = np[32];
            }
            uint32_t bh[4][4];
#pragma unroll
            for (int nb = 0; nb < 4; nb++) {
                int n = nb * 16 + b_n8;
                int col = c * 2 + b_k8;
                ldm4(bh[nb], sb + XTHI + (uint32_t)n * 512u + ((uint32_t)(col ^ (n & 7)) << 4));
            }
            const uint32_t* a0 = (const uint32_t*)&ca;
            const uint32_t* a1 = (const uint32_t*)&cb;
#pragma unroll
            for (int nt = 0; nt < 8; nt++) {
                const uint32_t* B0 = &bh[nt >> 1][(nt & 1) * 2];
                mma16816(acc[0][nt], a0, B0);
                mma16816(acc[1][nt], a1, B0);
            }
        }
        __syncthreads();   // prior-round epilogue reads of stg done before dump writes

        // ---- dump acc -> stg_t[pos][ch] fp16 (+bias), transposed ----
        {
            const __half* bias = (r < 2) ? (eb_h + r * 256) : db_h;
            __half* st = (__half*)(smem + AST);
#pragma unroll
            for (int mt = 0; mt < 2; mt++) {
                int r0 = wid * 32 + mt * 16 + (lid >> 2);
                float b0 = __half2float(bias[r0]), b8 = __half2float(bias[r0 + 8]);
#pragma unroll
                for (int nt = 0; nt < 8; nt++) {
                    int cc0 = nt * 8 + (lid & 3) * 2;
                    st[cc0 * 264 + r0]           = __float2half(acc[mt][nt][0] + b0);
                    st[(cc0 + 1) * 264 + r0]     = __float2half(acc[mt][nt][1] + b0);
                    st[cc0 * 264 + r0 + 8]       = __float2half(acc[mt][nt][2] + b8);
                    st[(cc0 + 1) * 264 + r0 + 8] = __float2half(acc[mt][nt][3] + b8);
                }
            }
        }
        __syncthreads();

        if (r < 2) {
            // ===== encoder epilogue (heads r*4 .. r*4+3) =====
#pragma unroll 1
            for (int hl4 = 0; hl4 < 4; hl4++) {
                int h = r * 4 + hl4;
                // score: thread (ip, tok=la, s=lb)
                const float* qg = latent + h * 128 + la * 32;
                const char* srow = smem + AST + (uint32_t)(ip * 4 + lb) * TSB + (uint32_t)hl4 * 128u;
                float sc = 0.f;
#pragma unroll
                for (int i = 0; i < 8; i++) {
                    uint4 u = *(const uint4*)(srow + i * 16);   // (k,v) pairs d=4i..4i+3
                    float4 q4 = *(const float4*)(qg + i * 4);
                    const __half2* hp = (const __half2*)&u;
                    float2 p0 = __half22float2(hp[0]);
                    float2 p1 = __half22float2(hp[1]);
                    float2 p2 = __half22float2(hp[2]);
                    float2 p3 = __half22float2(hp[3]);
                    sc += q4.x * p0.x + q4.y * p1.x + q4.z * p2.x + q4.w * p3.x;
                }
                float mx = sc;
                mx = fmaxf(mx, __shfl_xor_sync(FULL, mx, 1, 4));
                mx = fmaxf(mx, __shfl_xor_sync(FULL, mx, 2, 4));
                float ex = __expf(sc - mx);
                float ssum = ex;
                ssum += __shfl_xor_sync(FULL, ssum, 1, 4);
                ssum += __shfl_xor_sync(FULL, ssum, 2, 4);
                float av = ex / ssum;
                float a4[4];
#pragma unroll
                for (int s2 = 0; s2 < 4; s2++) a4[s2] = __shfl_sync(FULL, av, la * 4 + s2, 16);

                // v stage + packed spectral: thread (ip, tok=la, g=lb), pair p:
                // d0 = lb + 8p, d1 = d0 + 4; channels ch0 = h*32 + d0, ch1 = ch0 + 4.
#pragma unroll 1
                for (int p = 0; p < 4; p++) {
                    int d0 = lb + 8 * p, d1 = d0 + 4;
                    float ltv0 = latent[h * 128 + la * 32 + d0];   // q residual
                    float ltv1 = latent[h * 128 + la * 32 + d1];
#pragma unroll
                    for (int s2 = 0; s2 < 4; s2++) {
                        const char* vb = smem + AST + (uint32_t)(ip * 4 + s2) * TSB;
                        ltv0 += a4[s2] * __half2float(*(const __half*)(vb + (uint32_t)(hl4 * 128 + 4 * d0 + 2)));
                        ltv1 += a4[s2] * __half2float(*(const __half*)(vb + (uint32_t)(hl4 * 128 + 4 * d1 + 2)));
                    }
                    // packed Chebyshev: lanes = (ch0, ch1)
                    const __half2* wp = wsp2 + (h * 16 + p * 4 + lb) * 24;
                    float s1a, c1a, s1b, c1b;
                    __sincosf(ltv0 * PI_OVER_NB, &s1a, &c1a);
                    __sincosf(ltv1 * PI_OVER_NB, &s1b, &c1b);
                    ull s1p = pk2(s1a, s1b), c1p = pk2(c1a, c1b);
                    ull tcp = f2add(c1p, c1p);
                    ull accp = pk2h(wp[12]);                       // cos m=0 term
                    accp = f2fma(s1p, pk2h(wp[1]), accp);          // m=1 sin
                    accp = f2fma(c1p, pk2h(wp[13]), accp);         // m=1 cos
                    ull sm1 = s1p, cm1 = c1p;
                    ull sm2n = 0ULL;                               // -s0 = 0
                    ull cm2n = pk2(-1.f, -1.f);                    // -c0 = -1
#pragma unroll
                    for (int m = 2; m < 12; m++) {
                        ull sn = f2fma(tcp, sm1, sm2n);
                        ull cn = f2fma(tcp, cm1, cm2n);
                        accp = f2fma(sn, pk2h(wp[m]), accp);
                        accp = f2fma(cn, pk2h(wp[12 + m]), accp);
                        sm2n = sm1 ^ SGN2;
                        cm2n = cm1 ^ SGN2;
                        sm1 = sn; cm1 = cn;
                    }
                    float add0, add1;
                    upk2(add0, add1, accp);
                    int cch0 = h * 32 + d0;
                    char* ltbase = smem + LTT + (uint32_t)(ip * 4 + la) * TSB;
                    *(__half*)(ltbase + (uint32_t)cch0 * 2u)       = __float2half(ltv0 + add0);
                    *(__half*)(ltbase + (uint32_t)(cch0 + 4) * 2u) = __float2half(ltv1 + add1);
                }
            }
        } else {
            // ===== decoder epilogue (heads 0..7) =====
#pragma unroll 1
            for (int h = 0; h < 8; h++) {
                const char* dqp = smem + AST + (uint32_t)(ip * 4 + la) * TSB + (uint32_t)h * 64u;
                const char* ltp = smem + LTT + (uint32_t)(ip * 4 + lb) * TSB + (uint32_t)h * 64u;
                float sc = 0.f;
#pragma unroll
                for (int i = 0; i < 4; i++) {
                    uint4 ua = *(const uint4*)(dqp + i * 16);
                    uint4 ub = *(const uint4*)(ltp + i * 16);
                    const __half2* pa = (const __half2*)&ua;
                    const __half2* pb = (const __half2*)&ub;
#pragma unroll
                    for (int j2 = 0; j2 < 4; j2++) {
                        float2 fa = __half22float2(pa[j2]);
                        float2 fb = __half22float2(pb[j2]);
                        sc += fa.x * fb.x + fa.y * fb.y;
                    }
                }
                float mx = sc;
                mx = fmaxf(mx, __shfl_xor_sync(FULL, mx, 1, 4));
                mx = fmaxf(mx, __shfl_xor_sync(FULL, mx, 2, 4));
                float ex = __expf(sc - mx);
                float ssum = ex;
                ssum += __shfl_xor_sync(FULL, ssum, 1, 4);
                ssum += __shfl_xor_sync(FULL, ssum, 2, 4);
                float av = ex / ssum;
                float a4[4];
#pragma unroll
                for (int t2 = 0; t2 < 4; t2++) a4[t2] = __shfl_sync(FULL, av, la * 4 + t2, 16);

                // v stage: thread (ip, pos=la, cg=lb) -> ch = h*32 + lb*8 .. +7 (coalesced)
                float o[8];
#pragma unroll
                for (int i = 0; i < 8; i++) o[i] = 0.f;
#pragma unroll
                for (int t2 = 0; t2 < 4; t2++) {
                    uint4 lv = *(const uint4*)(smem + LTT + (uint32_t)(ip * 4 + t2) * TSB +
                                               (uint32_t)h * 64u + (uint32_t)lb * 16u);
                    const __half2* hp = (const __half2*)&lv;
                    float a = a4[t2];
#pragma unroll
                    for (int j2 = 0; j2 < 4; j2++) {
                        float2 f = __half22float2(hp[j2]);
                        o[2 * j2]     += a * f.x;
                        o[2 * j2 + 1] += a * f.y;
                    }
                }
                int j = ip * 4 + la;
                uint32_t xoff = (uint32_t)j * 512u + ((uint32_t)((h * 4 + lb) ^ (j & 7)) << 4);
                uint4 xv = *(const uint4*)(smem + XTHI + xoff);
                const __half2* xp = (const __half2*)&xv;
                float4 o0, o1;
                {
                    float2 f0 = __half22float2(xp[0]);
                    float2 f1 = __half22float2(xp[1]);
                    float2 f2 = __half22float2(xp[2]);
                    float2 f3 = __half22float2(xp[3]);
                    o0.x = o[0] + f0.x; o0.y = o[1] + f0.y;
                    o0.z = o[2] + f1.x; o0.w = o[3] + f1.y;
                    o1.x = o[4] + f2.x; o1.y = o[5] + f2.y;
                    o1.z = o[6] + f3.x; o1.w = o[7] + f3.y;
                }
                float* ob = og + (size_t)la * 262144 + (size_t)(hp0 + ip) * 256 + h * 32 + lb * 8;
                *(float4*)ob = o0;
                *(float4*)(ob + 4) = o1;
            }
        }
        // no trailing sync: next round's post-GEMM sync orders stg reuse
    }
}

extern "C" void kernel_launch(void* const* d_in, const int* in_sizes, int n_in,
                              void* d_out, int out_size)
{
    const float* x       = (const float*)d_in[0];
    const float* weights = (const float*)d_in[1];
    const float* latent  = (const float*)d_in[2];
    const float* enc_w   = (const float*)d_in[3];
    const float* enc_b   = (const float*)d_in[4];
    const float* dec_w   = (const float*)d_in[5];
    const float* dec_b   = (const float*)d_in[6];
    float* out = (float*)d_out;

    prep_kernel<<<(24 * 16 * 64 + 255) / 256, 256>>>(enc_w, dec_w);

    cudaFuncSetAttribute(NeuralSpectralBlock1d_4509715661385_kernel,
                         cudaFuncAttributeMaxDynamicSharedMemorySize, (int)SMEM_REQ);
    NeuralSpectralBlock1d_4509715661385_kernel<<<2048, THREADS, SMEM_REQ>>>(
        x, weights, latent, enc_b, dec_b, out);
}

// round 16
// speedup vs baseline: 1.0212x; 1.0212x over previous
#include <cuda_runtime.h>
#include <cuda_fp16.h>
#include <cstdint>

// NeuralSpectralBlock1d: single-pass fp16 mma.sync GEMM + PER-WARP 4-deep cp.async
// pipelines + packed f32x2 Chebyshev epilogue. Round 16: chunk loop unrolled x4
// with hoisted/invariant ldmatrix address math (alu-pipe diet). 2 CTAs/SM.
// CTA = 64 columns (16 patches) of one batch. Grid 2048, 256 threads.

#define THREADS 256

// SMEM layout (total 114176 B -> 2 CTAs/SM)
#define XTHI 0u          // x^T fp16 [64 j][256 k], 16B-swizzled       (32768)
#define AST  32768u      // GEMM: ring [4 buf][8 warp][1KB] ; epi: stg_t [64 pos][528B]
#define LTT  66560u      // lt_t fp16 [64 tok][528B]                    (33792)
#define WS   100352u     // spectral weights half2-pairs [128 pid][24]  (12288)
#define EB   112640u     // enc bias fp16 [512]                         (1024)
#define DB   113664u     // dec bias fp16 [256]                         (512)
#define SMEM_REQ 114176u

#define TSB 528u         // transposed row stride in bytes (264 halves)

typedef unsigned long long ull;

// fp16 weights: [kchunk 0..15][row 0..767][2 x 16B]; rows 0-511 enc, 512-767 dec.
// Chunk = 16 k. 16B cols: logical 0 = k0-7, 1 = k8-15; stored col = logical ^ ((row>>2)&1).
__device__ uint4 g_w16[16][768][2];

__global__ void prep_kernel(const float* __restrict__ enc_w, const float* __restrict__ dec_w) {
    int idx = blockIdx.x * blockDim.x + threadIdx.x;
    if (idx >= 768 * 32) return;
    int row = idx >> 5, c8 = idx & 31;           // c8: 8-k group
    const float* src = (row < 512) ? (enc_w + row * 256 + c8 * 8)
                                   : (dec_w + (row - 512) * 256 + c8 * 8);
    union { __half h[8]; uint4 u; } hi;
#pragma unroll
    for (int i = 0; i < 8; i++) hi.h[i] = __float2half(src[i]);
    int chunk = c8 >> 1, lc = c8 & 1;
    g_w16[chunk][row][lc ^ ((row >> 2) & 1)] = hi.u;
}

static __device__ __forceinline__ uint32_t smem_u32(const void* p) {
    uint32_t a;
    asm("{ .reg .u64 t; cvta.to.shared.u64 t, %1; cvt.u32.u64 %0, t; }" : "=r"(a) : "l"(p));
    return a;
}
static __device__ __forceinline__ void ldm4(uint32_t* d, uint32_t a) {
    asm volatile("ldmatrix.sync.aligned.m8n8.x4.shared.b16 {%0,%1,%2,%3}, [%4];"
                 : "=r"(d[0]), "=r"(d[1]), "=r"(d[2]), "=r"(d[3]) : "r"(a));
}
static __device__ __forceinline__ void mma16816(float* c, const uint32_t* a, const uint32_t* b) {
    asm volatile("mma.sync.aligned.m16n8k16.row.col.f32.f16.f16.f32 "
                 "{%0,%1,%2,%3}, {%4,%5,%6,%7}, {%8,%9}, {%0,%1,%2,%3};"
                 : "+f"(c[0]), "+f"(c[1]), "+f"(c[2]), "+f"(c[3])
                 : "r"(a[0]), "r"(a[1]), "r"(a[2]), "r"(a[3]), "r"(b[0]), "r"(b[1]));
}

// ---- packed f32x2 helpers ----
static __device__ __forceinline__ ull pk2(float lo, float hi) {
    ull r; asm("mov.b64 %0, {%1, %2};" : "=l"(r) : "f"(lo), "f"(hi)); return r;
}
static __device__ __forceinline__ ull pk2h(__half2 h) {
    float2 f = __half22float2(h); return pk2(f.x, f.y);
}
static __device__ __forceinline__ void upk2(float& lo, float& hi, ull v) {
    asm("mov.b64 {%0, %1}, %2;" : "=f"(lo), "=f"(hi) : "l"(v));
}
static __device__ __forceinline__ ull f2fma(ull a, ull b, ull c) {
    ull d; asm("fma.rn.f32x2 %0, %1, %2, %3;" : "=l"(d) : "l"(a), "l"(b), "l"(c)); return d;
}
static __device__ __forceinline__ ull f2add(ull a, ull b) {
    ull d; asm("add.rn.f32x2 %0, %1, %2;" : "=l"(d) : "l"(a), "l"(b)); return d;
}

// per-warp: stage THIS warp's 1KB slice (rows r*256 + wid*32 .. +31, k-chunk `chunk`)
// into ring buffer `buf`. Ring layout: [buf 0..3][wid 0..7][32 rows x 32B].
static __device__ __forceinline__ void stage_w(uint32_t sb, int r, int chunk, int buf,
                                               int wid, int lid) {
    const uint4* g = &g_w16[chunk][r * 256 + wid * 32 + lid][0];
    uint32_t d = sb + AST + (uint32_t)buf * 8192u + (uint32_t)wid * 1024u + (uint32_t)lid * 32u;
    asm volatile("cp.async.cg.shared.global [%0], [%1], 16;" :: "r"(d), "l"(g) : "memory");
    asm volatile("cp.async.cg.shared.global [%0], [%1], 16;" :: "r"(d + 16), "l"(g + 1) : "memory");
    asm volatile("cp.async.commit_group;" ::: "memory");
}

__global__ __launch_bounds__(THREADS, 2)
void NeuralSpectralBlock1d_4509715661385_kernel(
    const float* __restrict__ x, const float* __restrict__ weights,
    const float* __restrict__ latent, const float* __restrict__ enc_b,
    const float* __restrict__ dec_b, float* __restrict__ out)
{
    extern __shared__ char smem[];
    const uint32_t sb = smem_u32(smem);

    __half2* wsp2 = (__half2*)(smem + WS);   // [128 pid][24] pairs {w[ch0][m], w[ch0+4][m]}
    __half*  eb_h = (__half*)(smem + EB);
    __half*  db_h = (__half*)(smem + DB);

    const int tid = threadIdx.x;
    const int wid = tid >> 5, lid = tid & 31;
    const int bx = blockIdx.x;
    const int batch = bx >> 6;
    const int hp0 = (bx & 63) * 16;
    const int h0 = hp0 * 4;
    const float* xg = x + (size_t)batch * 256 * 4096 + h0;
    float* og = out + (size_t)batch * 256 * 4096;

    // per-warp prefetch of round-0 chunks 0..2 into ring buffers 0..2
    stage_w(sb, 0, 0, 0, wid, lid);
    stage_w(sb, 0, 1, 1, wid, lid);
    stage_w(sb, 0, 2, 2, wid, lid);

    // ---- loads: x tile fp16 swizzled, spectral weight pairs, biases ----
    for (int idx = tid; idx < 64 * 256; idx += THREADS) {
        int j = idx & 63, c = idx >> 6;
        float v = xg[(size_t)c * 4096 + j];
        uint32_t off = (uint32_t)j * 512u + ((uint32_t)((c >> 3) ^ (j & 7)) << 4) + (uint32_t)(c & 7) * 2u;
        *(__half*)(smem + XTHI + off) = __float2half(v);
    }
    // spectral weights, pair layout: pid = h*16 + p*4 + lb -> channels (ch0, ch0+4),
    // ch0 = h*32 + lb + 8p. wsp2[pid*24 + m] = {w[ch0][m], w[ch0+4][m]}
    for (int idx = tid; idx < 128 * 24; idx += THREADS) {
        int pid = idx / 24, m = idx - pid * 24;
        int lb_ = pid & 3, p_ = (pid >> 2) & 3, h_ = pid >> 4;
        int ch0 = h_ * 32 + lb_ + 8 * p_;
        wsp2[idx] = __floats2half2_rn(weights[ch0 * 24 + m], weights[(ch0 + 4) * 24 + m]);
    }
    for (int idx = tid; idx < 512; idx += THREADS) eb_h[idx] = __float2half(enc_b[idx]);
    for (int idx = tid; idx < 256; idx += THREADS) db_h[idx] = __float2half(dec_b[idx]);
    __syncthreads();

    const unsigned FULL = 0xFFFFFFFFu;
    const float PI_OVER_NB = 0.26179938779914943653855361527329f;  // pi/12
    const ull SGN2 = 0x8000000080000000ULL;

    // epilogue lane roles
    const int ip = tid >> 4;
    const int lane4 = tid & 15;
    const int la = lane4 >> 2, lb = lane4 & 3;

    // GEMM roles: warp wid owns rows wid*32..+31, all 64 cols
    const uint32_t a_row8 = (uint32_t)((lid & 7) + ((lid >> 3) & 1) * 8);
    const uint32_t a_half = (uint32_t)(lid >> 4);
    const int b_n8   = (lid & 7) + ((lid >> 4) & 1) * 8;
    const int b_k8   = (lid >> 3) & 1;

    // ---- hoisted invariant address components ----
    uint32_t a_off[2];                           // A lane offset within warp slice (const)
#pragma unroll
    for (int mt = 0; mt < 2; mt++) {
        int rowl = mt * 16 + (int)a_row8;
        uint32_t sw1 = (uint32_t)((rowl >> 2) & 1);
        a_off[mt] = (uint32_t)rowl * 32u + ((a_half ^ sw1) << 4);
    }
    const uint32_t ring0 = sb + AST + (uint32_t)wid * 1024u;   // + (c&3)*8192
    uint32_t b_base[4];                           // B row base per nb (const)
    uint32_t b_n7[4];                             // n&7 per nb (const)
#pragma unroll
    for (int nb = 0; nb < 4; nb++) {
        int n = nb * 16 + b_n8;
        b_base[nb] = sb + XTHI + (uint32_t)n * 512u;
        b_n7[nb] = (uint32_t)(n & 7);
    }

    // ================= 3 GEMM rounds: r=0,1 enc; r=2 dec =================
#pragma unroll 1
    for (int r = 0; r < 3; r++) {
        float acc[2][8][4];
#pragma unroll
        for (int mt = 0; mt < 2; mt++)
#pragma unroll
            for (int nt = 0; nt < 8; nt++)
#pragma unroll
                for (int q = 0; q < 4; q++) acc[mt][nt][q] = 0.f;

        // ---- barrier-free per-warp pipelined chunk loop (unrolled x4) ----
#pragma unroll 4
        for (int c = 0; c < 16; c++) {
            if (c < 14)       asm volatile("cp.async.wait_group 2;" ::: "memory");
            else if (c == 14) asm volatile("cp.async.wait_group 1;" ::: "memory");
            else              asm volatile("cp.async.wait_group 0;" ::: "memory");
            __syncwarp();                         // own warp's slice visible warp-wide
            if (c < 13) stage_w(sb, r, c + 3, (c + 3) & 3, wid, lid);

            const uint32_t ab = ring0 + (uint32_t)(c & 3) * 8192u;
            uint32_t ah[2][4];
            ldm4(ah[0], ab + a_off[0]);
            ldm4(ah[1], ab + a_off[1]);
            const uint32_t col = (uint32_t)(c * 2 + b_k8);
            uint32_t bh[4][4];
#pragma unroll
            for (int nb = 0; nb < 4; nb++)
                ldm4(bh[nb], b_base[nb] + ((col ^ b_n7[nb]) << 4));
#pragma unroll
            for (int mt = 0; mt < 2; mt++)
#pragma unroll
                for (int nt = 0; nt < 8; nt++)
                    mma16816(acc[mt][nt], ah[mt], &bh[nt >> 1][(nt & 1) * 2]);
        }
        __syncthreads();                          // all warps done with ring before dump

        // ---- dump acc -> stg_t[pos][ch] fp16 (+bias), transposed ----
        {
            const __half* bias = (r < 2) ? (eb_h + r * 256) : db_h;
            __half* st = (__half*)(smem + AST);
#pragma unroll
            for (int mt = 0; mt < 2; mt++) {
                int r0 = wid * 32 + mt * 16 + (lid >> 2);
                float b0 = __half2float(bias[r0]), b8 = __half2float(bias[r0 + 8]);
#pragma unroll
                for (int nt = 0; nt < 8; nt++) {
                    int cc0 = nt * 8 + (lid & 3) * 2;
                    st[cc0 * 264 + r0]           = __float2half(acc[mt][nt][0] + b0);
                    st[(cc0 + 1) * 264 + r0]     = __float2half(acc[mt][nt][1] + b0);
                    st[cc0 * 264 + r0 + 8]       = __float2half(acc[mt][nt][2] + b8);
                    st[(cc0 + 1) * 264 + r0 + 8] = __float2half(acc[mt][nt][3] + b8);
                }
            }
        }
        __syncthreads();

        if (r < 2) {
            // ===== encoder epilogue (heads r*4 .. r*4+3) =====
#pragma unroll 1
            for (int hl4 = 0; hl4 < 4; hl4++) {
                int h = r * 4 + hl4;
                // score: thread (ip, tok=la, s=lb)
                const float* qg = latent + h * 128 + la * 32;
                const char* srow = smem + AST + (uint32_t)(ip * 4 + lb) * TSB + (uint32_t)hl4 * 128u;
                float sc = 0.f;
#pragma unroll
                for (int i = 0; i < 8; i++) {
                    uint4 u = *(const uint4*)(srow + i * 16);   // (k,v) pairs d=4i..4i+3
                    float4 q4 = *(const float4*)(qg + i * 4);
                    const __half2* hp = (const __half2*)&u;
                    float2 p0 = __half22float2(hp[0]);
                    float2 p1 = __half22float2(hp[1]);
                    float2 p2 = __half22float2(hp[2]);
                    float2 p3 = __half22float2(hp[3]);
                    sc += q4.x * p0.x + q4.y * p1.x + q4.z * p2.x + q4.w * p3.x;
                }
                float mx = sc;
                mx = fmaxf(mx, __shfl_xor_sync(FULL, mx, 1, 4));
                mx = fmaxf(mx, __shfl_xor_sync(FULL, mx, 2, 4));
                float ex = __expf(sc - mx);
                float ssum = ex;
                ssum += __shfl_xor_sync(FULL, ssum, 1, 4);
                ssum += __shfl_xor_sync(FULL, ssum, 2, 4);
                float av = ex / ssum;
                float a4[4];
#pragma unroll
                for (int s2 = 0; s2 < 4; s2++) a4[s2] = __shfl_sync(FULL, av, la * 4 + s2, 16);

                // v stage + packed spectral: thread (ip, tok=la, g=lb), pair p:
                // d0 = lb + 8p, d1 = d0 + 4; channels ch0 = h*32 + d0, ch1 = ch0 + 4.
#pragma unroll 1
                for (int p = 0; p < 4; p++) {
                    int d0 = lb + 8 * p, d1 = d0 + 4;
                    float ltv0 = latent[h * 128 + la * 32 + d0];   // q residual
                    float ltv1 = latent[h * 128 + la * 32 + d1];
#pragma unroll
                    for (int s2 = 0; s2 < 4; s2++) {
                        const char* vb = smem + AST + (uint32_t)(ip * 4 + s2) * TSB;
                        ltv0 += a4[s2] * __half2float(*(const __half*)(vb + (uint32_t)(hl4 * 128 + 4 * d0 + 2)));
                        ltv1 += a4[s2] * __half2float(*(const __half*)(vb + (uint32_t)(hl4 * 128 + 4 * d1 + 2)));
                    }
                    // packed Chebyshev: lanes = (ch0, ch1)
                    const __half2* wp = wsp2 + (h * 16 + p * 4 + lb) * 24;
                    float s1a, c1a, s1b, c1b;
                    __sincosf(ltv0 * PI_OVER_NB, &s1a, &c1a);
                    __sincosf(ltv1 * PI_OVER_NB, &s1b, &c1b);
                    ull s1p = pk2(s1a, s1b), c1p = pk2(c1a, c1b);
                    ull tcp = f2add(c1p, c1p);
                    ull accp = pk2h(wp[12]);                       // cos m=0 term
                    accp = f2fma(s1p, pk2h(wp[1]), accp);          // m=1 sin
                    accp = f2fma(c1p, pk2h(wp[13]), accp);         // m=1 cos
                    ull sm1 = s1p, cm1 = c1p;
                    ull sm2n = 0ULL;                               // -s0 = 0
                    ull cm2n = pk2(-1.f, -1.f);                    // -c0 = -1
#pragma unroll
                    for (int m = 2; m < 12; m++) {
                        ull sn = f2fma(tcp, sm1, sm2n);
                        ull cn = f2fma(tcp, cm1, cm2n);
                        accp = f2fma(sn, pk2h(wp[m]), accp);
                        accp = f2fma(cn, pk2h(wp[12 + m]), accp);
                        sm2n = sm1 ^ SGN2;
                        cm2n = cm1 ^ SGN2;
                        sm1 = sn; cm1 = cn;
                    }
                    float add0, add1;
                    upk2(add0, add1, accp);
                    int cch0 = h * 32 + d0;
                    char* ltbase = smem + LTT + (uint32_t)(ip * 4 + la) * TSB;
                    *(__half*)(ltbase + (uint32_t)cch0 * 2u)       = __float2half(ltv0 + add0);
                    *(__half*)(ltbase + (uint32_t)(cch0 + 4) * 2u) = __float2half(ltv1 + add1);
                }
            }
        } else {
            // ===== decoder epilogue (heads 0..7) =====
#pragma unroll 1
            for (int h = 0; h < 8; h++) {
                const char* dqp = smem + AST + (uint32_t)(ip * 4 + la) * TSB + (uint32_t)h * 64u;
                const char* ltp = smem + LTT + (uint32_t)(ip * 4 + lb) * TSB + (uint32_t)h * 64u;
                float sc = 0.f;
#pragma unroll
                for (int i = 0; i < 4; i++) {
                    uint4 ua = *(const uint4*)(dqp + i * 16);
                    uint4 ub = *(const uint4*)(ltp + i * 16);
                    const __half2* pa = (const __half2*)&ua;
                    const __half2* pb = (const __half2*)&ub;
#pragma unroll
                    for (int j2 = 0; j2 < 4; j2++) {
                        float2 fa = __half22float2(pa[j2]);
                        float2 fb = __half22float2(pb[j2]);
                        sc += fa.x * fb.x + fa.y * fb.y;
                    }
                }
                float mx = sc;
                mx = fmaxf(mx, __shfl_xor_sync(FULL, mx, 1, 4));
                mx = fmaxf(mx, __shfl_xor_sync(FULL, mx, 2, 4));
                float ex = __expf(sc - mx);
                float ssum = ex;
                ssum += __shfl_xor_sync(FULL, ssum, 1, 4);
                ssum += __shfl_xor_sync(FULL, ssum, 2, 4);
                float av = ex / ssum;
                float a4[4];
#pragma unroll
                for (int t2 = 0; t2 < 4; t2++) a4[t2] = __shfl_sync(FULL, av, la * 4 + t2, 16);

                // v stage: thread (ip, pos=la, cg=lb) -> ch = h*32 + lb*8 .. +7 (coalesced)
                float o[8];
#pragma unroll
                for (int i = 0; i < 8; i++) o[i] = 0.f;
#pragma unroll
                for (int t2 = 0; t2 < 4; t2++) {
                    uint4 lv = *(const uint4*)(smem + LTT + (uint32_t)(ip * 4 + t2) * TSB +
                                               (uint32_t)h * 64u + (uint32_t)lb * 16u);
                    const __half2* hp = (const __half2*)&lv;
                    float a = a4[t2];
#pragma unroll
                    for (int j2 = 0; j2 < 4; j2++) {
                        float2 f = __half22float2(hp[j2]);
                        o[2 * j2]     += a * f.x;
                        o[2 * j2 + 1] += a * f.y;
                    }
                }
                int j = ip * 4 + la;
                uint32_t xoff = (uint32_t)j * 512u + ((uint32_t)((h * 4 + lb) ^ (j & 7)) << 4);
                uint4 xv = *(const uint4*)(smem + XTHI + xoff);
                const __half2* xp = (const __half2*)&xv;
                float4 o0, o1;
                {
                    float2 f0 = __half22float2(xp[0]);
                    float2 f1 = __half22float2(xp[1]);
                    float2 f2 = __half22float2(xp[2]);
                    float2 f3 = __half22float2(xp[3]);
                    o0.x = o[0] + f0.x; o0.y = o[1] + f0.y;
                    o0.z = o[2] + f1.x; o0.w = o[3] + f1.y;
                    o1.x = o[4] + f2.x; o1.y = o[5] + f2.y;
                    o1.z = o[6] + f3.x; o1.w = o[7] + f3.y;
                }
                float* ob = og + (size_t)la * 262144 + (size_t)(hp0 + ip) * 256 + h * 32 + lb * 8;
                *(float4*)ob = o0;
                *(float4*)(ob + 4) = o1;
            }
        }
        __syncthreads();                         // stg_t (ring region) free for next round

        if (r < 2) {                             // per-warp prefetch next round chunks 0..2
            stage_w(sb, r + 1, 0, 0, wid, lid);
            stage_w(sb, r + 1, 1, 1, wid, lid);
            stage_w(sb, r + 1, 2, 2, wid, lid);
        }
    }
}

extern "C" void kernel_launch(void* const* d_in, const int* in_sizes, int n_in,
                              void* d_out, int out_size)
{
    const float* x       = (const float*)d_in[0];
    const float* weights = (const float*)d_in[1];
    const float* latent  = (const float*)d_in[2];
    const float* enc_w   = (const float*)d_in[3];
    const float* enc_b   = (const float*)d_in[4];
    const float* dec_w   = (const float*)d_in[5];
    const float* dec_b   = (const float*)d_in[6];
    float* out = (float*)d_out;

    prep_kernel<<<(768 * 32 + 255) / 256, 256>>>(enc_w, dec_w);

    cudaFuncSetAttribute(NeuralSpectralBlock1d_4509715661385_kernel,
                         cudaFuncAttributeMaxDynamicSharedMemorySize, (int)SMEM_REQ);
    NeuralSpectralBlock1d_4509715661385_kernel<<<2048, THREADS, SMEM_REQ>>>(
        x, weights, latent, enc_b, dec_b, out);
}

// round 17
// speedup vs baseline: 1.0469x; 1.0251x over previous
#include <cuda_runtime.h>
#include <cuda_fp16.h>
#include <cstdint>

// NeuralSpectralBlock1d: single-pass fp16 mma.sync GEMM + per-warp 4-deep cp.async
// pipelines. Round 17: enc k/v rows DE-INTERLEAVED (k d0-31 then v d0-31 per head
// block, permuted in prep) -> vectorized k-score + packed f32x2 epilogue math.
// 2 CTAs/SM. CTA = 64 columns (16 patches) of one batch. Grid 2048, 256 threads.

#define THREADS 256

// SMEM layout (total 114176 B -> 2 CTAs/SM)
#define XTHI 0u          // x^T fp16 [64 j][256 k], 16B-swizzled       (32768)
#define AST  32768u      // GEMM: ring [4 buf][8 warp][1KB] ; epi: stg_t [64 pos][528B]
#define LTT  66560u      // lt_t fp16 [64 tok][528B]                    (33792)
#define WS   100352u     // spectral weights half2-pairs [128 pid][24]  (12288)
#define EB   112640u     // enc bias fp16 [512] (PERMUTED)              (1024)
#define DB   113664u     // dec bias fp16 [256]                         (512)
#define SMEM_REQ 114176u

#define TSB 528u         // transposed row stride in bytes (264 halves)

typedef unsigned long long ull;

// fp16 weights: [kchunk 0..15][row 0..767][2 x 16B]; rows 0-511 enc (PERMUTED:
// within each 64-row head block, rows 0-31 = k (orig even), 32-63 = v (orig odd)),
// rows 512-767 dec (unchanged).
// Chunk = 16 k. 16B cols: logical 0 = k0-7, 1 = k8-15; stored col = logical ^ ((row>>2)&1).
__device__ uint4 g_w16[16][768][2];

__global__ void prep_kernel(const float* __restrict__ enc_w, const float* __restrict__ dec_w) {
    int idx = blockIdx.x * blockDim.x + threadIdx.x;
    if (idx >= 768 * 32) return;
    int row = idx >> 5, c8 = idx & 31;           // c8: 8-k group
    int srow;                                     // source row in enc_w/dec_w
    const float* src;
    if (row < 512) {
        // de-interleave perm: row = h*64 + t*32 + d  <-  orig = h*64 + 2d + t
        srow = (row & ~63) + ((row & 31) * 2) + ((row >> 5) & 1);
        src = enc_w + srow * 256 + c8 * 8;
    } else {
        src = dec_w + (row - 512) * 256 + c8 * 8;
    }
    union { __half h[8]; uint4 u; } hi;
#pragma unroll
    for (int i = 0; i < 8; i++) hi.h[i] = __float2half(src[i]);
    int chunk = c8 >> 1, lc = c8 & 1;
    g_w16[chunk][row][lc ^ ((row >> 2) & 1)] = hi.u;
}

static __device__ __forceinline__ uint32_t smem_u32(const void* p) {
    uint32_t a;
    asm("{ .reg .u64 t; cvta.to.shared.u64 t, %1; cvt.u32.u64 %0, t; }" : "=r"(a) : "l"(p));
    return a;
}
static __device__ __forceinline__ void ldm4(uint32_t* d, uint32_t a) {
    asm volatile("ldmatrix.sync.aligned.m8n8.x4.shared.b16 {%0,%1,%2,%3}, [%4];"
                 : "=r"(d[0]), "=r"(d[1]), "=r"(d[2]), "=r"(d[3]) : "r"(a));
}
static __device__ __forceinline__ void mma16816(float* c, const uint32_t* a, const uint32_t* b) {
    asm volatile("mma.sync.aligned.m16n8k16.row.col.f32.f16.f16.f32 "
                 "{%0,%1,%2,%3}, {%4,%5,%6,%7}, {%8,%9}, {%0,%1,%2,%3};"
                 : "+f"(c[0]), "+f"(c[1]), "+f"(c[2]), "+f"(c[3])
                 : "r"(a[0]), "r"(a[1]), "r"(a[2]), "r"(a[3]), "r"(b[0]), "r"(b[1]));
}

// ---- packed f32x2 helpers ----
static __device__ __forceinline__ ull pk2(float lo, float hi) {
    ull r; asm("mov.b64 %0, {%1, %2};" : "=l"(r) : "f"(lo), "f"(hi)); return r;
}
static __device__ __forceinline__ ull pk2h(__half2 h) {
    float2 f = __half22float2(h); return pk2(f.x, f.y);
}
static __device__ __forceinline__ void upk2(float& lo, float& hi, ull v) {
    asm("mov.b64 {%0, %1}, %2;" : "=f"(lo), "=f"(hi) : "l"(v));
}
static __device__ __forceinline__ ull f2fma(ull a, ull b, ull c) {
    ull d; asm("fma.rn.f32x2 %0, %1, %2, %3;" : "=l"(d) : "l"(a), "l"(b), "l"(c)); return d;
}
static __device__ __forceinline__ ull f2add(ull a, ull b) {
    ull d; asm("add.rn.f32x2 %0, %1, %2;" : "=l"(d) : "l"(a), "l"(b)); return d;
}
static __device__ __forceinline__ float hsum2(ull v) {
    float lo, hi; upk2(lo, hi, v); return lo + hi;
}

// per-warp: stage THIS warp's 1KB slice (rows r*256 + wid*32 .. +31, k-chunk `chunk`)
// into ring buffer `buf`. Ring layout: [buf 0..3][wid 0..7][32 rows x 32B].
static __device__ __forceinline__ void stage_w(uint32_t sb, int r, int chunk, int buf,
                                               int wid, int lid) {
    const uint4* g = &g_w16[chunk][r * 256 + wid * 32 + lid][0];
    uint32_t d = sb + AST + (uint32_t)buf * 8192u + (uint32_t)wid * 1024u + (uint32_t)lid * 32u;
    asm volatile("cp.async.cg.shared.global [%0], [%1], 16;" :: "r"(d), "l"(g) : "memory");
    asm volatile("cp.async.cg.shared.global [%0], [%1], 16;" :: "r"(d + 16), "l"(g + 1) : "memory");
    asm volatile("cp.async.commit_group;" ::: "memory");
}

__global__ __launch_bounds__(THREADS, 2)
void NeuralSpectralBlock1d_4509715661385_kernel(
    const float* __restrict__ x, const float* __restrict__ weights,
    const float* __restrict__ latent, const float* __restrict__ enc_b,
    const float* __restrict__ dec_b, float* __restrict__ out)
{
    extern __shared__ char smem[];
    const uint32_t sb = smem_u32(smem);

    __half2* wsp2 = (__half2*)(smem + WS);   // [128 pid][24] pairs {w[ch0][m], w[ch0+4][m]}
    __half*  eb_h = (__half*)(smem + EB);    // permuted enc bias
    __half*  db_h = (__half*)(smem + DB);

    const int tid = threadIdx.x;
    const int wid = tid >> 5, lid = tid & 31;
    const int bx = blockIdx.x;
    const int batch = bx >> 6;
    const int hp0 = (bx & 63) * 16;
    const int h0 = hp0 * 4;
    const float* xg = x + (size_t)batch * 256 * 4096 + h0;
    float* og = out + (size_t)batch * 256 * 4096;

    // per-warp prefetch of round-0 chunks 0..2 into ring buffers 0..2
    stage_w(sb, 0, 0, 0, wid, lid);
    stage_w(sb, 0, 1, 1, wid, lid);
    stage_w(sb, 0, 2, 2, wid, lid);

    // ---- loads: x tile fp16 swizzled, spectral weight pairs, biases ----
    for (int idx = tid; idx < 64 * 256; idx += THREADS) {
        int j = idx & 63, c = idx >> 6;
        float v = xg[(size_t)c * 4096 + j];
        uint32_t off = (uint32_t)j * 512u + ((uint32_t)((c >> 3) ^ (j & 7)) << 4) + (uint32_t)(c & 7) * 2u;
        *(__half*)(smem + XTHI + off) = __float2half(v);
    }
    // spectral weights, pair layout: pid = h*16 + p*4 + lb -> channels (ch0, ch0+4),
    // ch0 = h*32 + lb + 8p. wsp2[pid*24 + m] = {w[ch0][m], w[ch0+4][m]}
    for (int idx = tid; idx < 128 * 24; idx += THREADS) {
        int pid = idx / 24, m = idx - pid * 24;
        int lb_ = pid & 3, p_ = (pid >> 2) & 3, h_ = pid >> 4;
        int ch0 = h_ * 32 + lb_ + 8 * p_;
        wsp2[idx] = __floats2half2_rn(weights[ch0 * 24 + m], weights[(ch0 + 4) * 24 + m]);
    }
    // enc bias in PERMUTED row order: eb_h[g] = enc_b[orig(g)]
    for (int idx = tid; idx < 512; idx += THREADS) {
        int orig = (idx & ~63) + ((idx & 31) * 2) + ((idx >> 5) & 1);
        eb_h[idx] = __float2half(enc_b[orig]);
    }
    for (int idx = tid; idx < 256; idx += THREADS) db_h[idx] = __float2half(dec_b[idx]);
    __syncthreads();

    const unsigned FULL = 0xFFFFFFFFu;
    const float PI_OVER_NB = 0.26179938779914943653855361527329f;  // pi/12
    const ull SGN2 = 0x8000000080000000ULL;

    // epilogue lane roles
    const int ip = tid >> 4;
    const int lane4 = tid & 15;
    const int la = lane4 >> 2, lb = lane4 & 3;

    // GEMM roles: warp wid owns rows wid*32..+31, all 64 cols
    const uint32_t a_row8 = (uint32_t)((lid & 7) + ((lid >> 3) & 1) * 8);
    const uint32_t a_half = (uint32_t)(lid >> 4);
    const int b_n8   = (lid & 7) + ((lid >> 4) & 1) * 8;
    const int b_k8   = (lid >> 3) & 1;

    // ================= 3 GEMM rounds: r=0,1 enc; r=2 dec =================
#pragma unroll 1
    for (int r = 0; r < 3; r++) {
        float acc[2][8][4];
#pragma unroll
        for (int mt = 0; mt < 2; mt++)
#pragma unroll
            for (int nt = 0; nt < 8; nt++)
#pragma unroll
                for (int q = 0; q < 4; q++) acc[mt][nt][q] = 0.f;

        // ---- barrier-free per-warp pipelined chunk loop ----
#pragma unroll 1
        for (int c = 0; c < 16; c++) {
            if (c < 14)       asm volatile("cp.async.wait_group 2;" ::: "memory");
            else if (c == 14) asm volatile("cp.async.wait_group 1;" ::: "memory");
            else              asm volatile("cp.async.wait_group 0;" ::: "memory");
            __syncwarp();                         // own warp's slice visible warp-wide
            if (c < 13) stage_w(sb, r, c + 3, (c + 3) & 3, wid, lid);

            const uint32_t ab = sb + AST + (uint32_t)(c & 3) * 8192u + (uint32_t)wid * 1024u;
            uint32_t ah[2][4];
#pragma unroll
            for (int mt = 0; mt < 2; mt++) {
                int rowl = mt * 16 + (int)a_row8;
                uint32_t sw1 = (uint32_t)((rowl >> 2) & 1);
                ldm4(ah[mt], ab + (uint32_t)rowl * 32u + ((a_half ^ sw1) << 4));
            }
            uint32_t bh[4][4];
#pragma unroll
            for (int nb = 0; nb < 4; nb++) {
                int n = nb * 16 + b_n8;
                int col = c * 2 + b_k8;
                ldm4(bh[nb], sb + XTHI + (uint32_t)n * 512u + ((uint32_t)(col ^ (n & 7)) << 4));
            }
#pragma unroll
            for (int mt = 0; mt < 2; mt++)
#pragma unroll
                for (int nt = 0; nt < 8; nt++)
                    mma16816(acc[mt][nt], ah[mt], &bh[nt >> 1][(nt & 1) * 2]);
        }
        __syncthreads();                          // all warps done with ring before dump

        // ---- dump acc -> stg_t[pos][ch] fp16 (+bias), transposed ----
        {
            const __half* bias = (r < 2) ? (eb_h + r * 256) : db_h;
            __half* st = (__half*)(smem + AST);
#pragma unroll
            for (int mt = 0; mt < 2; mt++) {
                int r0 = wid * 32 + mt * 16 + (lid >> 2);
                float b0 = __half2float(bias[r0]), b8 = __half2float(bias[r0 + 8]);
#pragma unroll
                for (int nt = 0; nt < 8; nt++) {
                    int cc0 = nt * 8 + (lid & 3) * 2;
                    st[cc0 * 264 + r0]           = __float2half(acc[mt][nt][0] + b0);
                    st[(cc0 + 1) * 264 + r0]     = __float2half(acc[mt][nt][1] + b0);
                    st[cc0 * 264 + r0 + 8]       = __float2half(acc[mt][nt][2] + b8);
                    st[(cc0 + 1) * 264 + r0 + 8] = __float2half(acc[mt][nt][3] + b8);
                }
            }
        }
        __syncthreads();

        if (r < 2) {
            // ===== encoder epilogue (heads r*4 .. r*4+3), de-interleaved k/v =====
            // head block hl4: bytes [hl4*128, hl4*128+64) = k d0..31, [+64, +128) = v d0..31
#pragma unroll 1
            for (int hl4 = 0; hl4 < 4; hl4++) {
                int h = r * 4 + hl4;
                // score: thread (ip, tok=la, s=lb) — vectorized k, packed fma
                const float* qg = latent + h * 128 + la * 32;
                const char* srow = smem + AST + (uint32_t)(ip * 4 + lb) * TSB + (uint32_t)hl4 * 128u;
                ull sc2 = 0ULL;
#pragma unroll
                for (int i = 0; i < 4; i++) {
                    uint4 u = *(const uint4*)(srow + i * 16);    // k halves d=8i..8i+7
                    float4 qa = *(const float4*)(qg + i * 8);
                    float4 qb = *(const float4*)(qg + i * 8 + 4);
                    const __half2* hp = (const __half2*)&u;
                    sc2 = f2fma(pk2(qa.x, qa.y), pk2h(hp[0]), sc2);
                    sc2 = f2fma(pk2(qa.z, qa.w), pk2h(hp[1]), sc2);
                    sc2 = f2fma(pk2(qb.x, qb.y), pk2h(hp[2]), sc2);
                    sc2 = f2fma(pk2(qb.z, qb.w), pk2h(hp[3]), sc2);
                }
                float sc = hsum2(sc2);
                float mx = sc;
                mx = fmaxf(mx, __shfl_xor_sync(FULL, mx, 1, 4));
                mx = fmaxf(mx, __shfl_xor_sync(FULL, mx, 2, 4));
                float ex = __expf(sc - mx);
                float ssum = ex;
                ssum += __shfl_xor_sync(FULL, ssum, 1, 4);
                ssum += __shfl_xor_sync(FULL, ssum, 2, 4);
                float av = ex / ssum;
                float a4[4];
#pragma unroll
                for (int s2 = 0; s2 < 4; s2++) a4[s2] = __shfl_sync(FULL, av, la * 4 + s2, 16);

                // v stage + packed spectral: thread (ip, tok=la, g=lb), pair p:
                // d0 = lb + 8p, d1 = d0 + 4; v at byte hl4*128 + 64 + 2*d.
#pragma unroll 1
                for (int p = 0; p < 4; p++) {
                    int d0 = lb + 8 * p, d1 = d0 + 4;
                    ull ltv01 = pk2(latent[h * 128 + la * 32 + d0],
                                    latent[h * 128 + la * 32 + d1]);   // q residual
#pragma unroll
                    for (int s2 = 0; s2 < 4; s2++) {
                        const char* vb = smem + AST + (uint32_t)(ip * 4 + s2) * TSB +
                                         (uint32_t)(hl4 * 128 + 64);
                        float v0 = __half2float(*(const __half*)(vb + 2 * d0));
                        float v1 = __half2float(*(const __half*)(vb + 2 * d1));
                        ltv01 = f2fma(pk2(a4[s2], a4[s2]), pk2(v0, v1), ltv01);
                    }
                    float ltv0, ltv1;
                    upk2(ltv0, ltv1, ltv01);
                    // packed Chebyshev: lanes = (ch0, ch1)
                    const __half2* wp = wsp2 + (h * 16 + p * 4 + lb) * 24;
                    float s1a, c1a, s1b, c1b;
                    __sincosf(ltv0 * PI_OVER_NB, &s1a, &c1a);
                    __sincosf(ltv1 * PI_OVER_NB, &s1b, &c1b);
                    ull s1p = pk2(s1a, s1b), c1p = pk2(c1a, c1b);
                    ull tcp = f2add(c1p, c1p);
                    ull accp = pk2h(wp[12]);                       // cos m=0 term
                    accp = f2fma(s1p, pk2h(wp[1]), accp);          // m=1 sin
                    accp = f2fma(c1p, pk2h(wp[13]), accp);         // m=1 cos
                    ull sm1 = s1p, cm1 = c1p;
                    ull sm2n = 0ULL;                               // -s0 = 0
                    ull cm2n = pk2(-1.f, -1.f);                    // -c0 = -1
#pragma unroll
                    for (int m = 2; m < 12; m++) {
                        ull sn = f2fma(tcp, sm1, sm2n);
                        ull cn = f2fma(tcp, cm1, cm2n);
                        accp = f2fma(sn, pk2h(wp[m]), accp);
                        accp = f2fma(cn, pk2h(wp[12 + m]), accp);
                        sm2n = sm1 ^ SGN2;
                        cm2n = cm1 ^ SGN2;
                        sm1 = sn; cm1 = cn;
                    }
                    float add0, add1;
                    upk2(add0, add1, accp);
                    int cch0 = h * 32 + d0;
                    char* ltbase = smem + LTT + (uint32_t)(ip * 4 + la) * TSB;
                    *(__half*)(ltbase + (uint32_t)cch0 * 2u)       = __float2half(ltv0 + add0);
                    *(__half*)(ltbase + (uint32_t)(cch0 + 4) * 2u) = __float2half(ltv1 + add1);
                }
            }
        } else {
            // ===== decoder epilogue (heads 0..7), packed fma =====
#pragma unroll 1
            for (int h = 0; h < 8; h++) {
                const char* dqp = smem + AST + (uint32_t)(ip * 4 + la) * TSB + (uint32_t)h * 64u;
                const char* ltp = smem + LTT + (uint32_t)(ip * 4 + lb) * TSB + (uint32_t)h * 64u;
                ull sc2 = 0ULL;
#pragma unroll
                for (int i = 0; i < 4; i++) {
                    uint4 ua = *(const uint4*)(dqp + i * 16);
                    uint4 ub = *(const uint4*)(ltp + i * 16);
                    const __half2* pa = (const __half2*)&ua;
                    const __half2* pb = (const __half2*)&ub;
#pragma unroll
                    for (int j2 = 0; j2 < 4; j2++)
                        sc2 = f2fma(pk2h(pa[j2]), pk2h(pb[j2]), sc2);
                }
                float sc = hsum2(sc2);
                float mx = sc;
                mx = fmaxf(mx, __shfl_xor_sync(FULL, mx, 1, 4));
                mx = fmaxf(mx, __shfl_xor_sync(FULL, mx, 2, 4));
                float ex = __expf(sc - mx);
                float ssum = ex;
                ssum += __shfl_xor_sync(FULL, ssum, 1, 4);
                ssum += __shfl_xor_sync(FULL, ssum, 2, 4);
                float av = ex / ssum;
                float a4[4];
#pragma unroll
                for (int t2 = 0; t2 < 4; t2++) a4[t2] = __shfl_sync(FULL, av, la * 4 + t2, 16);

                // v stage: thread (ip, pos=la, cg=lb) -> ch = h*32 + lb*8 .. +7 (coalesced)
                ull o2[4];
#pragma unroll
                for (int i = 0; i < 4; i++) o2[i] = 0ULL;
#pragma unroll
                for (int t2 = 0; t2 < 4; t2++) {
                    uint4 lv = *(const uint4*)(smem + LTT + (uint32_t)(ip * 4 + t2) * TSB +
                                               (uint32_t)h * 64u + (uint32_t)lb * 16u);
                    const __half2* hp = (const __half2*)&lv;
                    ull ad = pk2(a4[t2], a4[t2]);
#pragma unroll
                    for (int j2 = 0; j2 < 4; j2++)
                        o2[j2] = f2fma(ad, pk2h(hp[j2]), o2[j2]);
                }
                int j = ip * 4 + la;
                uint32_t xoff = (uint32_t)j * 512u + ((uint32_t)((h * 4 + lb) ^ (j & 7)) << 4);
                uint4 xv = *(const uint4*)(smem + XTHI + xoff);
                const __half2* xp = (const __half2*)&xv;
                float4 o0, o1;
                {
                    float a0, a1;
                    upk2(a0, a1, f2add(o2[0], pk2h(xp[0]))); o0.x = a0; o0.y = a1;
                    upk2(a0, a1, f2add(o2[1], pk2h(xp[1]))); o0.z = a0; o0.w = a1;
                    upk2(a0, a1, f2add(o2[2], pk2h(xp[2]))); o1.x = a0; o1.y = a1;
                    upk2(a0, a1, f2add(o2[3], pk2h(xp[3]))); o1.z = a0; o1.w = a1;
                }
                float* ob = og + (size_t)la * 262144 + (size_t)(hp0 + ip) * 256 + h * 32 + lb * 8;
                *(float4*)ob = o0;
                *(float4*)(ob + 4) = o1;
            }
        }
        __syncthreads();                         // stg_t (ring region) free for next round

        if (r < 2) {                             // per-warp prefetch next round chunks 0..2
            stage_w(sb, r + 1, 0, 0, wid, lid);
            stage_w(sb, r + 1, 1, 1, wid, lid);
            stage_w(sb, r + 1, 2, 2, wid, lid);
        }
    }
}

extern "C" void kernel_launch(void* const* d_in, const int* in_sizes, int n_in,
                              void* d_out, int out_size)
{
    const float* x       = (const float*)d_in[0];
    const float* weights = (const float*)d_in[1];
    const float* latent  = (const float*)d_in[2];
    const float* enc_w   = (const float*)d_in[3];
    const float* enc_b   = (const float*)d_in[4];
    const float* dec_w   = (const float*)d_in[5];
    const float* dec_b   = (const float*)d_in[6];
    float* out = (float*)d_out;

    prep_kernel<<<(768 * 32 + 255) / 256, 256>>>(enc_w, dec_w);

    cudaFuncSetAttribute(NeuralSpectralBlock1d_4509715661385_kernel,
                         cudaFuncAttributeMaxDynamicSharedMemorySize, (int)SMEM_REQ);
    NeuralSpectralBlock1d_4509715661385_kernel<<<2048, THREADS, SMEM_REQ>>>(
        x, weights, latent, enc_b, dec_b, out);
}